// round 12
// baseline (speedup 1.0000x reference)
#include <cuda_runtime.h>

#define BSZ 64
#define HID 300
#define SEQ 64
#define VOC 100000
#define NB  148
#define THR 704                  // 22 warps
#define WST 356                  // ws k-row stride in ull
#define KC  12                   // k per chunk; 25 chunks exactly

typedef unsigned long long ull;

// ---------------- scratch ----------------
__device__ float2 g_hp[2][HID * 32];            // packed h, double buffered
__device__ float2 g_egi[SEQ * 900 * 32];        // precomputed encoder input gates (+bias)
__device__ ull    g_best2[2][BSZ];              // per-step argmax keys, double buffered
__device__ unsigned g_barcnt, g_bargen;

// ---------------- helpers ----------------
__device__ __forceinline__ unsigned ordf(float f) {
    unsigned u = __float_as_uint(f);
    return (u & 0x80000000u) ? ~u : (u | 0x80000000u);
}
__device__ __forceinline__ ull pack2(float lo, float hi) {
    ull r;
    asm("mov.b64 %0, {%1,%2};" : "=l"(r) : "f"(lo), "f"(hi));
    return r;
}
__device__ __forceinline__ void unpack2(ull v, float& lo, float& hi) {
    asm("mov.b64 {%0,%1}, %2;" : "=f"(lo), "=f"(hi) : "l"(v));
}
__device__ __forceinline__ ull ffma2(ull a, ull b, ull c) {
    ull d;
    asm("fma.rn.f32x2 %0, %1, %2, %3;" : "=l"(d) : "l"(a), "l"(b), "l"(c));
    return d;
}

// grid-wide barrier; all NB blocks co-resident (1 block/SM).
__device__ __forceinline__ void grid_bar() {
    __threadfence();
    __syncthreads();
    if (threadIdx.x == 0) {
        unsigned gen = atomicAdd(&g_bargen, 0u);
        if (atomicAdd(&g_barcnt, 1u) == (unsigned)(NB - 1)) {
            atomicExch(&g_barcnt, 0u);
            __threadfence();
            atomicAdd(&g_bargen, 1u);
        } else {
            while (atomicAdd(&g_bargen, 0u) == gen) __nanosleep(64);
        }
    }
    __syncthreads();
}

// ---------------- init ----------------
__global__ void k_init() {
    int i = blockIdx.x * blockDim.x + threadIdx.x;
    if (i < HID * 32) g_hp[0][i] = make_float2(0.f, 0.f);
    if (i == 0) { g_barcnt = 0u; g_bargen = 0u; }
}

// ---------------- encoder input-gate pre-GEMM (all 64 steps, one launch) -------
#define SM_ENCPRE (16320 + 31680 + 256)
__global__ void k_encpre(const int* __restrict__ input, const float* __restrict__ emb,
                         const float* __restrict__ W, const float* __restrict__ bias) {
    extern __shared__ char sm[];
    float2* x_s = (float2*)sm;               // [60][34]
    float2* w_s = (float2*)(sm + 16320);     // [60][66] duplicated
    int* sid    = (int*)(sm + 16320 + 31680);
    const int tid = threadIdx.x;
    const int t = blockIdx.y, j0 = blockIdx.x * 64;
    if (tid < BSZ) sid[tid] = input[t * BSZ + tid];
    __syncthreads();
    const int tx = tid & 15, ty = tid >> 4;
    ull acc[2][4] = {};
    for (int k0 = 0; k0 < HID; k0 += 60) {
        for (int idx = tid; idx < 32 * 60; idx += 256) {
            int k = idx >> 5, bp = idx & 31;
            float e0 = emb[(long)sid[2 * bp] * HID + k0 + k];
            float e1 = emb[(long)sid[2 * bp + 1] * HID + k0 + k];
            x_s[k * 34 + bp] = make_float2(e0, e1);
        }
        for (int idx = tid; idx < 64 * 15; idx += 256) {
            int j = idx / 15, q = idx % 15;
            int jg = j0 + j;
            float4 w = (jg < 900) ? *(const float4*)&W[(long)jg * HID + k0 + q * 4]
                                  : make_float4(0, 0, 0, 0);
            w_s[(q * 4 + 0) * 66 + j] = make_float2(w.x, w.x);
            w_s[(q * 4 + 1) * 66 + j] = make_float2(w.y, w.y);
            w_s[(q * 4 + 2) * 66 + j] = make_float2(w.z, w.z);
            w_s[(q * 4 + 3) * 66 + j] = make_float2(w.w, w.w);
        }
        __syncthreads();
#pragma unroll 4
        for (int k = 0; k < 60; k++) {
            ull xp0 = *(const ull*)&x_s[k * 34 + ty];
            ull xp1 = *(const ull*)&x_s[k * 34 + ty + 16];
            ulonglong2 wA = *(const ulonglong2*)&w_s[k * 66 + tx * 4];
            ulonglong2 wB = *(const ulonglong2*)&w_s[k * 66 + tx * 4 + 2];
            acc[0][0] = ffma2(xp0, wA.x, acc[0][0]);
            acc[1][0] = ffma2(xp1, wA.x, acc[1][0]);
            acc[0][1] = ffma2(xp0, wA.y, acc[0][1]);
            acc[1][1] = ffma2(xp1, wA.y, acc[1][1]);
            acc[0][2] = ffma2(xp0, wB.x, acc[0][2]);
            acc[1][2] = ffma2(xp1, wB.x, acc[1][2]);
            acc[0][3] = ffma2(xp0, wB.y, acc[0][3]);
            acc[1][3] = ffma2(xp1, wB.y, acc[1][3]);
        }
        __syncthreads();
    }
#pragma unroll
    for (int jj = 0; jj < 4; jj++) {
        int j = j0 + tx * 4 + jj;
        if (j >= 900) continue;
        float bb = bias[j];
#pragma unroll
        for (int p = 0; p < 2; p++) {
            int bp = ty + 16 * p;
            float a, b; unpack2(acc[p][jj], a, b);
            g_egi[((long)t * 900 + j) * 32 + bp] = make_float2(a + bb, b + bb);
        }
    }
}

// ---------------- persistent encoder (512 thr): weights resident ---------------
#define SM_ENC (76800 + 21600 + 9216 + 32)
__global__ void __launch_bounds__(512, 1) k_enc(const float* __restrict__ Whh,
                                                const float* __restrict__ bhh) {
    extern __shared__ char sm[];
    float2* Hn = (float2*)sm;
    float2* Wg = (float2*)(sm + 76800);
    ull*   red = (ull*)(sm + 76800 + 21600);
    const int tid = threadIdx.x, warp = tid >> 5, lane = tid & 31;
    const int bid = blockIdx.x;
    const int nr = (bid < 4) ? 3 : 2;

    for (int i = tid; i < nr * 3 * 75; i += 512) {
        int row = i / 75, q = i % 75;
        int rl = row / 3, g = row % 3;
        int grow = g * HID + bid + rl * NB;
        float4 w = *(const float4*)&Whh[(long)grow * HID + q * 4];
        float2* d2 = &Wg[row * 300 + q * 4];
        d2[0] = make_float2(w.x, w.x); d2[1] = make_float2(w.y, w.y);
        d2[2] = make_float2(w.z, w.z); d2[3] = make_float2(w.w, w.w);
    }
    __syncthreads();

    for (int t = 0; t < SEQ; t++) {
        const int par = t & 1;
        for (int i = tid; i < 4800; i += 512)
            ((uint4*)Hn)[i] = __ldcg((const uint4*)&g_hp[par][0] + i);
        __syncthreads();
        const int rl = warp >> 2, kq = warp & 3;
        if (rl < nr) {
            ull a0 = 0, a1 = 0, a2 = 0;
            const float2* wb = &Wg[rl * 900];
            const int kend = kq * 75 + 75;
#pragma unroll 3
            for (int k = kq * 75; k < kend; k++) {
                ull hv = *(const ull*)&Hn[k * 32 + lane];
                a0 = ffma2(hv, *(const ull*)&wb[k], a0);
                a1 = ffma2(hv, *(const ull*)&wb[300 + k], a1);
                a2 = ffma2(hv, *(const ull*)&wb[600 + k], a2);
            }
            red[((rl * 4 + kq) * 3 + 0) * 32 + lane] = a0;
            red[((rl * 4 + kq) * 3 + 1) * 32 + lane] = a1;
            red[((rl * 4 + kq) * 3 + 2) * 32 + lane] = a2;
        }
        __syncthreads();
        if (warp < nr) {
            const int row = bid + warp * NB;
            float s[3][2];
#pragma unroll
            for (int g = 0; g < 3; g++) {
                float acx = 0.f, acy = 0.f;
#pragma unroll
                for (int kq2 = 0; kq2 < 4; kq2++) {
                    float a, b;
                    unpack2(red[((warp * 4 + kq2) * 3 + g) * 32 + lane], a, b);
                    acx += a; acy += b;
                }
                s[g][0] = acx; s[g][1] = acy;
            }
            float bhr = bhh[row], bhz = bhh[HID + row], bhn = bhh[2 * HID + row];
            float2 er = g_egi[((long)t * 900 + row) * 32 + lane];
            float2 ez = g_egi[((long)t * 900 + 300 + row) * 32 + lane];
            float2 en = g_egi[((long)t * 900 + 600 + row) * 32 + lane];
            float2 hold = Hn[row * 32 + lane];
            float gr[2] = {er.x, er.y}, gz[2] = {ez.x, ez.y}, gn[2] = {en.x, en.y};
            float ho[2] = {hold.x, hold.y}, o2[2];
#pragma unroll
            for (int p = 0; p < 2; p++) {
                float r = 1.f / (1.f + expf(-(gr[p] + s[0][p] + bhr)));
                float z = 1.f / (1.f + expf(-(gz[p] + s[1][p] + bhz)));
                float n = tanhf(gn[p] + r * (s[2][p] + bhn));
                o2[p] = (1.f - z) * n + z * ho[p];
            }
            g_hp[par ^ 1][row * 32 + lane] = make_float2(o2[0], o2[1]);
        }
        grid_bar();
    }
}

// ---------------- persistent decoder, 704 threads ------------------------------
// Phase B smem: hb[300][48] ull @0 (115200B), ws 2x[KC][WST] ull @115200 (68352B),
//               sb [22][64] ull @183552 (11264B)
// Phase A smem (overlaid): Hn @0, X @76800, red @153600, sid @172032, WgA @172288
#define OFF_WS 115200
#define OFF_SB 183552
#define OFF_X  76800
#define OFF_RED 153600
#define OFF_SID 172032
#define OFF_WGA 172288
#define SM_DEC 194816
__global__ void __launch_bounds__(THR, 1) k_dec(
    const float* __restrict__ emb,
    const float* __restrict__ Wih, const float* __restrict__ Whh,
    const float* __restrict__ bih, const float* __restrict__ bhh,
    const float* __restrict__ outW, const float* __restrict__ outb,
    float* __restrict__ out) {
    extern __shared__ char sm[];
    ull*    hb  = (ull*)sm;
    ull*    ws  = (ull*)(sm + OFF_WS);
    ull*    sb  = (ull*)(sm + OFF_SB);
    float2* Hn  = (float2*)sm;
    float*  X   = (float*)(sm + OFF_X);
    ull*    red = (ull*)(sm + OFF_RED);
    int*    sid = (int*)(sm + OFF_SID);
    float*  WgA = (float*)(sm + OFF_WGA);

    const int tid = threadIdx.x, warp = tid >> 5, lane = tid & 31;
    const int bid = blockIdx.x;
    const int nr = (bid < 4) ? 3 : 2;
    const int vb = bid * 675 + (bid < 100 ? bid : 100);
    const int bg = tid & 7;          // b-group: b = bg*8 .. bg*8+7
    const int vql = tid >> 3;        // 0..87 (v-quad within pass)

    const int i2 = tid + THR;
    const int r1 = tid / 3, q1 = tid % 3;
    const int r2 = i2 / 3,  q2 = i2 % 3;
    const bool has2 = (i2 < 1056);

    for (int d = 0; d < SEQ; d++) {
        const int par = d & 1;
        // ===== phase A: ids, stage Wg/h/x, GRU step =====
        if (tid < BSZ) {
            int myid = 0;
            if (d > 0) {
                ull key = __ldcg(&g_best2[par ^ 1][tid]);
                myid = (int)(0xFFFFFFFFu - (unsigned)key);
                if (bid == 0) out[(d - 1) * BSZ + tid] = (float)myid;
            }
            sid[tid] = myid;
            if (bid == 0) g_best2[par][tid] = 0ULL;
        }
        for (int i = tid; i < nr * 6 * 75; i += THR) {
            int row = i / 75, q = i % 75;
            int rl = row / 6, g = row % 6;
            const float* W = (g < 3) ? Wih : Whh;
            int grow = (g % 3) * HID + bid + rl * NB;
            float4 w = __ldg((const float4*)&W[(long)grow * HID + q * 4]);
            float* dd = &WgA[row * 300 + q * 4];
            dd[0] = w.x; dd[1] = w.y; dd[2] = w.z; dd[3] = w.w;
        }
        for (int i = tid; i < 4800; i += THR)
            ((uint4*)Hn)[i] = __ldcg((const uint4*)&g_hp[par][0] + i);
        __syncthreads();
        for (int i = tid; i < 64 * 75; i += THR) {
            int b = i / 75, q = i % 75;
            float4 e = __ldg((const float4*)&emb[(long)sid[b] * HID + q * 4]);
            X[(q * 4 + 0) * 64 + b] = fmaxf(e.x, 0.f);
            X[(q * 4 + 1) * 64 + b] = fmaxf(e.y, 0.f);
            X[(q * 4 + 2) * 64 + b] = fmaxf(e.z, 0.f);
            X[(q * 4 + 3) * 64 + b] = fmaxf(e.w, 0.f);
        }
        __syncthreads();
        if (warp < 16) {
            const int rl = warp >> 2, kq = warp & 3;
            if (rl < nr) {
                ull a6[6] = {};
                const float* wb = &WgA[rl * 1800];
                const int kend = kq * 75 + 75;
                for (int k = kq * 75; k < kend; k++) {
                    ull hv = *(const ull*)&Hn[k * 32 + lane];
                    ull xv = *(const ull*)&X[k * 64 + lane * 2];
#pragma unroll
                    for (int g = 0; g < 6; g++) {
                        float w = wb[g * 300 + k];
                        a6[g] = ffma2((g < 3) ? xv : hv, pack2(w, w), a6[g]);
                    }
                }
#pragma unroll
                for (int g = 0; g < 6; g++)
                    red[((rl * 4 + kq) * 6 + g) * 32 + lane] = a6[g];
            }
        }
        __syncthreads();
        if (warp < nr) {
            const int row = bid + warp * NB;
            float s[6][2];
#pragma unroll
            for (int g = 0; g < 6; g++) {
                float acx = 0.f, acy = 0.f;
#pragma unroll
                for (int kq2 = 0; kq2 < 4; kq2++) {
                    float a, b;
                    unpack2(red[((warp * 4 + kq2) * 6 + g) * 32 + lane], a, b);
                    acx += a; acy += b;
                }
                s[g][0] = acx; s[g][1] = acy;
            }
            float bir = bih[row], biz = bih[HID + row], bin = bih[2 * HID + row];
            float bhr = bhh[row], bhz = bhh[HID + row], bhn = bhh[2 * HID + row];
            float2 hold = Hn[row * 32 + lane];
            float ho[2] = {hold.x, hold.y}, o2[2];
#pragma unroll
            for (int p = 0; p < 2; p++) {
                float r = 1.f / (1.f + expf(-(s[0][p] + bir + s[3][p] + bhr)));
                float z = 1.f / (1.f + expf(-(s[1][p] + biz + s[4][p] + bhz)));
                float n = tanhf(s[2][p] + bin + r * (s[5][p] + bhn));
                o2[p] = (1.f - z) * n + z * ho[p];
            }
            g_hp[par ^ 1][row * 32 + lane] = make_float2(o2[0], o2[1]);
        }
        grid_bar();

        // ===== phase B: logits + argmax =====
        for (int i = tid; i < 9600; i += THR) {
            int k = i >> 5, bp = i & 31;
            ull hv = __ldcg((const ull*)&g_hp[par ^ 1][k * 32 + bp]);
            hb[k * 48 + (bp >> 2) * 6 + (bp & 3)] = hv;
        }
        for (int pass = 0; pass < 2; pass++) {
            const int v0 = vb + (pass * 88 + vql) * 4;   // thread's 4 v
            const int vs = vb + pass * 352;              // stage base
            const int v1 = vs + r1, v2 = vs + r2;
            const bool ok1 = v1 < VOC;
            const bool ok2 = has2 && (v2 < VOC);
            float4 wr1, wr2;
            wr1 = ok1 ? __ldg((const float4*)&outW[(long)v1 * HID + q1 * 4])
                      : make_float4(0, 0, 0, 0);
            wr2 = ok2 ? __ldg((const float4*)&outW[(long)v2 * HID + q2 * 4])
                      : make_float4(0, 0, 0, 0);
            ull acc[4][4] = {};
            for (int c = 0; c < 25; c++) {
                const int buf = (pass * 25 + c) & 1;
                ull* wd = ws + buf * (KC * WST);
                {
                    ull* p1 = &wd[(q1 * 4) * WST + r1];
                    p1[0] = pack2(wr1.x, wr1.x); p1[WST] = pack2(wr1.y, wr1.y);
                    p1[2 * WST] = pack2(wr1.z, wr1.z); p1[3 * WST] = pack2(wr1.w, wr1.w);
                    if (has2) {
                        ull* p2 = &wd[(q2 * 4) * WST + r2];
                        p2[0] = pack2(wr2.x, wr2.x); p2[WST] = pack2(wr2.y, wr2.y);
                        p2[2 * WST] = pack2(wr2.z, wr2.z); p2[3 * WST] = pack2(wr2.w, wr2.w);
                    }
                }
                __syncthreads();
                if (c < 24) {
                    int kn = (c + 1) * KC;
                    if (ok1) wr1 = __ldg((const float4*)&outW[(long)v1 * HID + kn + q1 * 4]);
                    if (ok2) wr2 = __ldg((const float4*)&outW[(long)v2 * HID + kn + q2 * 4]);
                }
                const ull* wrow = wd + vql * 4;
                const ull* hrow = hb + (long)c * KC * 48 + bg * 6;
#pragma unroll
                for (int k = 0; k < KC; k++) {
                    ulonglong2 wA = *(const ulonglong2*)(wrow + k * WST);
                    ulonglong2 wB = *(const ulonglong2*)(wrow + k * WST + 2);
                    ulonglong2 hA = *(const ulonglong2*)(hrow + k * 48);
                    ulonglong2 hB = *(const ulonglong2*)(hrow + k * 48 + 2);
                    ull wv[4] = {wA.x, wA.y, wB.x, wB.y};
                    ull hh[4] = {hA.x, hA.y, hB.x, hB.y};
#pragma unroll
                    for (int vi = 0; vi < 4; vi++)
#pragma unroll
                        for (int bp = 0; bp < 4; bp++)
                            acc[vi][bp] = ffma2(wv[vi], hh[bp], acc[vi][bp]);
                }
                __syncthreads();
            }
            // epilogue: bias + keys for this pass
            ull bst[8] = {};
#pragma unroll
            for (int vi = 0; vi < 4; vi++) {
                int v = v0 + vi;
                if (v >= VOC) continue;
                float bb = __ldg(&outb[v]);
                unsigned lowb = 0xFFFFFFFFu - (unsigned)v;
#pragma unroll
                for (int bp = 0; bp < 4; bp++) {
                    float x, y; unpack2(acc[vi][bp], x, y);
                    ull kx = ((ull)ordf(x + bb) << 32) | lowb;
                    ull ky = ((ull)ordf(y + bb) << 32) | lowb;
                    if (kx > bst[2 * bp])     bst[2 * bp]     = kx;
                    if (ky > bst[2 * bp + 1]) bst[2 * bp + 1] = ky;
                }
            }
            // reduce across lanes sharing bg (lane, lane+8, +16, +24)
#pragma unroll
            for (int off = 16; off >= 8; off >>= 1)
#pragma unroll
                for (int j = 0; j < 8; j++) {
                    ull o = __shfl_down_sync(0xFFFFFFFFu, bst[j], off);
                    if (o > bst[j]) bst[j] = o;
                }
            if (lane < 8) {
                ull* row = &sb[warp * 64 + lane * 8];
#pragma unroll
                for (int j = 0; j < 8; j++) {
                    ull cur = (pass == 0) ? 0ULL : row[j];
                    row[j] = (bst[j] > cur) ? bst[j] : cur;
                }
            }
        }
        __syncthreads();
        if (tid < BSZ) {
            ull m = 0;
#pragma unroll 2
            for (int w = 0; w < 22; w++) {
                ull k = sb[w * 64 + tid];
                if (k > m) m = k;
            }
            atomicMax(&g_best2[par][tid], m);
        }
        grid_bar();
    }
    if (blockIdx.x == 0 && tid < BSZ) {
        ull key = __ldcg(&g_best2[(SEQ - 1) & 1][tid]);
        out[(SEQ - 1) * BSZ + tid] = (float)(int)(0xFFFFFFFFu - (unsigned)key);
    }
}

// ---------------- launch ----------------
extern "C" void kernel_launch(void* const* d_in, const int* in_sizes, int n_in,
                              void* d_out, int out_size) {
    const int*   input = (const int*)d_in[0];
    const float* emb   = (const float*)d_in[1];
    const float* eWih  = (const float*)d_in[2];
    const float* eWhh  = (const float*)d_in[3];
    const float* ebih  = (const float*)d_in[4];
    const float* ebhh  = (const float*)d_in[5];
    const float* dWih  = (const float*)d_in[6];
    const float* dWhh  = (const float*)d_in[7];
    const float* dbih  = (const float*)d_in[8];
    const float* dbhh  = (const float*)d_in[9];
    const float* outW  = (const float*)d_in[10];
    const float* outb  = (const float*)d_in[11];
    float* out = (float*)d_out;

    cudaFuncSetAttribute(k_encpre, cudaFuncAttributeMaxDynamicSharedMemorySize, SM_ENCPRE);
    cudaFuncSetAttribute(k_enc,    cudaFuncAttributeMaxDynamicSharedMemorySize, SM_ENC);
    cudaFuncSetAttribute(k_dec,    cudaFuncAttributeMaxDynamicSharedMemorySize, SM_DEC);

    k_init<<<38, 256>>>();
    k_encpre<<<dim3(15, 64), 256, SM_ENCPRE>>>(input, emb, eWih, ebih);
    k_enc<<<NB, 512, SM_ENC>>>(eWhh, ebhh);
    k_dec<<<NB, THR, SM_DEC>>>(emb, dWih, dWhh, dbih, dbhh, outW, outb, out);
}

// round 13
// speedup vs baseline: 1.1686x; 1.1686x over previous
#include <cuda_runtime.h>

#define BSZ 64
#define HID 300
#define SEQ 64
#define VOC 100000
#define NB  148
#define THR 704                  // 22 warps

typedef unsigned long long ull;

// ---------------- scratch ----------------
__device__ float2 g_hp[2][HID * 32];            // packed h, double buffered
__device__ float2 g_egi[SEQ * 900 * 32];        // precomputed encoder input gates (+bias)
__device__ ull    g_best2[2][BSZ];              // per-step argmax keys, double buffered
__device__ unsigned g_barcnt, g_bargen;

// ---------------- helpers ----------------
__device__ __forceinline__ unsigned ordf(float f) {
    unsigned u = __float_as_uint(f);
    return (u & 0x80000000u) ? ~u : (u | 0x80000000u);
}
__device__ __forceinline__ ull pack2(float lo, float hi) {
    ull r;
    asm("mov.b64 %0, {%1,%2};" : "=l"(r) : "f"(lo), "f"(hi));
    return r;
}
__device__ __forceinline__ void unpack2(ull v, float& lo, float& hi) {
    asm("mov.b64 {%0,%1}, %2;" : "=f"(lo), "=f"(hi) : "l"(v));
}
__device__ __forceinline__ ull ffma2(ull a, ull b, ull c) {
    ull d;
    asm("fma.rn.f32x2 %0, %1, %2, %3;" : "=l"(d) : "l"(a), "l"(b), "l"(c));
    return d;
}

// grid-wide barrier; all NB blocks co-resident (1 block/SM).
__device__ __forceinline__ void grid_bar() {
    __threadfence();
    __syncthreads();
    if (threadIdx.x == 0) {
        unsigned gen = atomicAdd(&g_bargen, 0u);
        if (atomicAdd(&g_barcnt, 1u) == (unsigned)(NB - 1)) {
            atomicExch(&g_barcnt, 0u);
            __threadfence();
            atomicAdd(&g_bargen, 1u);
        } else {
            while (atomicAdd(&g_bargen, 0u) == gen) __nanosleep(64);
        }
    }
    __syncthreads();
}

// ---------------- init ----------------
__global__ void k_init() {
    int i = blockIdx.x * blockDim.x + threadIdx.x;
    if (i < HID * 32) g_hp[0][i] = make_float2(0.f, 0.f);
    if (i == 0) { g_barcnt = 0u; g_bargen = 0u; }
}

// ---------------- encoder input-gate pre-GEMM (all 64 steps, one launch) -------
#define SM_ENCPRE (16320 + 31680 + 256)
__global__ void k_encpre(const int* __restrict__ input, const float* __restrict__ emb,
                         const float* __restrict__ W, const float* __restrict__ bias) {
    extern __shared__ char sm[];
    float2* x_s = (float2*)sm;               // [60][34]
    float2* w_s = (float2*)(sm + 16320);     // [60][66] duplicated
    int* sid    = (int*)(sm + 16320 + 31680);
    const int tid = threadIdx.x;
    const int t = blockIdx.y, j0 = blockIdx.x * 64;
    if (tid < BSZ) sid[tid] = input[t * BSZ + tid];
    __syncthreads();
    const int tx = tid & 15, ty = tid >> 4;
    ull acc[2][4] = {};
    for (int k0 = 0; k0 < HID; k0 += 60) {
        for (int idx = tid; idx < 32 * 60; idx += 256) {
            int k = idx >> 5, bp = idx & 31;
            float e0 = emb[(long)sid[2 * bp] * HID + k0 + k];
            float e1 = emb[(long)sid[2 * bp + 1] * HID + k0 + k];
            x_s[k * 34 + bp] = make_float2(e0, e1);
        }
        for (int idx = tid; idx < 64 * 15; idx += 256) {
            int j = idx / 15, q = idx % 15;
            int jg = j0 + j;
            float4 w = (jg < 900) ? *(const float4*)&W[(long)jg * HID + k0 + q * 4]
                                  : make_float4(0, 0, 0, 0);
            w_s[(q * 4 + 0) * 66 + j] = make_float2(w.x, w.x);
            w_s[(q * 4 + 1) * 66 + j] = make_float2(w.y, w.y);
            w_s[(q * 4 + 2) * 66 + j] = make_float2(w.z, w.z);
            w_s[(q * 4 + 3) * 66 + j] = make_float2(w.w, w.w);
        }
        __syncthreads();
#pragma unroll 4
        for (int k = 0; k < 60; k++) {
            ull xp0 = *(const ull*)&x_s[k * 34 + ty];
            ull xp1 = *(const ull*)&x_s[k * 34 + ty + 16];
            ulonglong2 wA = *(const ulonglong2*)&w_s[k * 66 + tx * 4];
            ulonglong2 wB = *(const ulonglong2*)&w_s[k * 66 + tx * 4 + 2];
            acc[0][0] = ffma2(xp0, wA.x, acc[0][0]);
            acc[1][0] = ffma2(xp1, wA.x, acc[1][0]);
            acc[0][1] = ffma2(xp0, wA.y, acc[0][1]);
            acc[1][1] = ffma2(xp1, wA.y, acc[1][1]);
            acc[0][2] = ffma2(xp0, wB.x, acc[0][2]);
            acc[1][2] = ffma2(xp1, wB.x, acc[1][2]);
            acc[0][3] = ffma2(xp0, wB.y, acc[0][3]);
            acc[1][3] = ffma2(xp1, wB.y, acc[1][3]);
        }
        __syncthreads();
    }
#pragma unroll
    for (int jj = 0; jj < 4; jj++) {
        int j = j0 + tx * 4 + jj;
        if (j >= 900) continue;
        float bb = bias[j];
#pragma unroll
        for (int p = 0; p < 2; p++) {
            int bp = ty + 16 * p;
            float a, b; unpack2(acc[p][jj], a, b);
            g_egi[((long)t * 900 + j) * 32 + bp] = make_float2(a + bb, b + bb);
        }
    }
}

// ---------------- persistent encoder (512 thr): weights resident ---------------
#define SM_ENC (76800 + 21600 + 9216 + 32)
__global__ void __launch_bounds__(512, 1) k_enc(const float* __restrict__ Whh,
                                                const float* __restrict__ bhh) {
    extern __shared__ char sm[];
    float2* Hn = (float2*)sm;
    float2* Wg = (float2*)(sm + 76800);
    ull*   red = (ull*)(sm + 76800 + 21600);
    const int tid = threadIdx.x, warp = tid >> 5, lane = tid & 31;
    const int bid = blockIdx.x;
    const int nr = (bid < 4) ? 3 : 2;

    for (int i = tid; i < nr * 3 * 75; i += 512) {
        int row = i / 75, q = i % 75;
        int rl = row / 3, g = row % 3;
        int grow = g * HID + bid + rl * NB;
        float4 w = *(const float4*)&Whh[(long)grow * HID + q * 4];
        float2* d2 = &Wg[row * 300 + q * 4];
        d2[0] = make_float2(w.x, w.x); d2[1] = make_float2(w.y, w.y);
        d2[2] = make_float2(w.z, w.z); d2[3] = make_float2(w.w, w.w);
    }
    __syncthreads();

    for (int t = 0; t < SEQ; t++) {
        const int par = t & 1;
        for (int i = tid; i < 4800; i += 512)
            ((uint4*)Hn)[i] = __ldcg((const uint4*)&g_hp[par][0] + i);
        __syncthreads();
        const int rl = warp >> 2, kq = warp & 3;
        if (rl < nr) {
            ull a0 = 0, a1 = 0, a2 = 0;
            const float2* wb = &Wg[rl * 900];
            const int kend = kq * 75 + 75;
#pragma unroll 3
            for (int k = kq * 75; k < kend; k++) {
                ull hv = *(const ull*)&Hn[k * 32 + lane];
                a0 = ffma2(hv, *(const ull*)&wb[k], a0);
                a1 = ffma2(hv, *(const ull*)&wb[300 + k], a1);
                a2 = ffma2(hv, *(const ull*)&wb[600 + k], a2);
            }
            red[((rl * 4 + kq) * 3 + 0) * 32 + lane] = a0;
            red[((rl * 4 + kq) * 3 + 1) * 32 + lane] = a1;
            red[((rl * 4 + kq) * 3 + 2) * 32 + lane] = a2;
        }
        __syncthreads();
        if (warp < nr) {
            const int row = bid + warp * NB;
            float s[3][2];
#pragma unroll
            for (int g = 0; g < 3; g++) {
                float acx = 0.f, acy = 0.f;
#pragma unroll
                for (int kq2 = 0; kq2 < 4; kq2++) {
                    float a, b;
                    unpack2(red[((warp * 4 + kq2) * 3 + g) * 32 + lane], a, b);
                    acx += a; acy += b;
                }
                s[g][0] = acx; s[g][1] = acy;
            }
            float bhr = bhh[row], bhz = bhh[HID + row], bhn = bhh[2 * HID + row];
            float2 er = g_egi[((long)t * 900 + row) * 32 + lane];
            float2 ez = g_egi[((long)t * 900 + 300 + row) * 32 + lane];
            float2 en = g_egi[((long)t * 900 + 600 + row) * 32 + lane];
            float2 hold = Hn[row * 32 + lane];
            float gr[2] = {er.x, er.y}, gz[2] = {ez.x, ez.y}, gn[2] = {en.x, en.y};
            float ho[2] = {hold.x, hold.y}, o2[2];
#pragma unroll
            for (int p = 0; p < 2; p++) {
                float r = 1.f / (1.f + expf(-(gr[p] + s[0][p] + bhr)));
                float z = 1.f / (1.f + expf(-(gz[p] + s[1][p] + bhz)));
                float n = tanhf(gn[p] + r * (s[2][p] + bhn));
                o2[p] = (1.f - z) * n + z * ho[p];
            }
            g_hp[par ^ 1][row * 32 + lane] = make_float2(o2[0], o2[1]);
        }
        grid_bar();
    }
}

// ---------------- persistent decoder, 704 threads ------------------------------
// smem layout:
//   WgA  @0       (21600)  persistent decoder GRU weights, staged once
//   hb   @21632   (115200) phase B: h dup-pairs, 48-ull k-stride (bank-clean)
//   Hn   @21632   (76800)  phase A (overlays hb)
//   X    @98432   (79200)  phase A: relu(emb), row stride 66 floats
//   sb   @136832  (11264)  phase B: per-warp argmax table (overlays X; disjoint in time)
//   red  @177632  (18432)  phase A
//   sid  @196064  (256)
#define OFF_HB  21632
#define OFF_X   98432
#define OFF_SB  136832
#define OFF_RED 177632
#define OFF_SID 196064
#define SM_DEC  196352
__global__ void __launch_bounds__(THR, 1) k_dec(
    const float* __restrict__ emb,
    const float* __restrict__ Wih, const float* __restrict__ Whh,
    const float* __restrict__ bih, const float* __restrict__ bhh,
    const float* __restrict__ outW, const float* __restrict__ outb,
    float* __restrict__ out) {
    extern __shared__ char sm[];
    float*  WgA = (float*)sm;
    ull*    hb  = (ull*)(sm + OFF_HB);
    float2* Hn  = (float2*)(sm + OFF_HB);
    float*  X   = (float*)(sm + OFF_X);
    ull*    sb  = (ull*)(sm + OFF_SB);
    ull*    red = (ull*)(sm + OFF_RED);
    int*    sid = (int*)(sm + OFF_SID);

    const int tid = threadIdx.x, warp = tid >> 5, lane = tid & 31;
    const int bid = blockIdx.x;
    const int nr = (bid < 4) ? 3 : 2;
    const int vb = bid * 675 + (bid < 100 ? bid : 100);
    const int bg = tid & 7;          // b-group: b = bg*8 .. bg*8+7
    const int vql = tid >> 3;        // 0..87 (v-quad within pass)

    // stage decoder GRU weights ONCE (persistent for all 64 steps)
    for (int i = tid; i < nr * 6 * 75; i += THR) {
        int row = i / 75, q = i % 75;
        int rl = row / 6, g = row % 6;
        const float* W = (g < 3) ? Wih : Whh;
        int grow = (g % 3) * HID + bid + rl * NB;
        float4 w = __ldg((const float4*)&W[(long)grow * HID + q * 4]);
        float* dd = &WgA[row * 300 + q * 4];
        dd[0] = w.x; dd[1] = w.y; dd[2] = w.z; dd[3] = w.w;
    }
    __syncthreads();

    for (int d = 0; d < SEQ; d++) {
        const int par = d & 1;
        // ===== phase A: ids, stage h/x, GRU step =====
        if (tid < BSZ) {
            int myid = 0;
            if (d > 0) {
                ull key = __ldcg(&g_best2[par ^ 1][tid]);
                myid = (int)(0xFFFFFFFFu - (unsigned)key);
                if (bid == 0) out[(d - 1) * BSZ + tid] = (float)myid;
            }
            sid[tid] = myid;
            if (bid == 0) g_best2[par][tid] = 0ULL;
        }
        for (int i = tid; i < 4800; i += THR)
            ((uint4*)Hn)[i] = __ldcg((const uint4*)&g_hp[par][0] + i);
        __syncthreads();
        for (int i = tid; i < 64 * 75; i += THR) {
            int b = i / 75, q = i % 75;
            float4 e = __ldg((const float4*)&emb[(long)sid[b] * HID + q * 4]);
            X[(q * 4 + 0) * 66 + b] = fmaxf(e.x, 0.f);
            X[(q * 4 + 1) * 66 + b] = fmaxf(e.y, 0.f);
            X[(q * 4 + 2) * 66 + b] = fmaxf(e.z, 0.f);
            X[(q * 4 + 3) * 66 + b] = fmaxf(e.w, 0.f);
        }
        __syncthreads();
        if (warp < 16) {
            const int rl = warp >> 2, kq = warp & 3;
            if (rl < nr) {
                ull a6[6] = {};
                const float* wb = &WgA[rl * 1800];
                const int kend = kq * 75 + 75;
                for (int k = kq * 75; k < kend; k++) {
                    ull hv = *(const ull*)&Hn[k * 32 + lane];
                    ull xv = *(const ull*)&X[k * 66 + lane * 2];
#pragma unroll
                    for (int g = 0; g < 6; g++) {
                        float w = wb[g * 300 + k];
                        a6[g] = ffma2((g < 3) ? xv : hv, pack2(w, w), a6[g]);
                    }
                }
#pragma unroll
                for (int g = 0; g < 6; g++)
                    red[((rl * 4 + kq) * 6 + g) * 32 + lane] = a6[g];
            }
        }
        __syncthreads();
        if (warp < nr) {
            const int row = bid + warp * NB;
            float s[6][2];
#pragma unroll
            for (int g = 0; g < 6; g++) {
                float acx = 0.f, acy = 0.f;
#pragma unroll
                for (int kq2 = 0; kq2 < 4; kq2++) {
                    float a, b;
                    unpack2(red[((warp * 4 + kq2) * 6 + g) * 32 + lane], a, b);
                    acx += a; acy += b;
                }
                s[g][0] = acx; s[g][1] = acy;
            }
            float bir = bih[row], biz = bih[HID + row], bin = bih[2 * HID + row];
            float bhr = bhh[row], bhz = bhh[HID + row], bhn = bhh[2 * HID + row];
            float2 hold = Hn[row * 32 + lane];
            float ho[2] = {hold.x, hold.y}, o2[2];
#pragma unroll
            for (int p = 0; p < 2; p++) {
                float r = 1.f / (1.f + expf(-(s[0][p] + bir + s[3][p] + bhr)));
                float z = 1.f / (1.f + expf(-(s[1][p] + biz + s[4][p] + bhz)));
                float n = tanhf(s[2][p] + bin + r * (s[5][p] + bhn));
                o2[p] = (1.f - z) * n + z * ho[p];
            }
            g_hp[par ^ 1][row * 32 + lane] = make_float2(o2[0], o2[1]);
        }
        grid_bar();

        // ===== phase B: logits + argmax (no smem w staging, no inner barriers) =====
        for (int i = tid; i < 9600; i += THR) {
            int k = i >> 5, bp = i & 31;
            ull hv = __ldcg((const ull*)&g_hp[par ^ 1][k * 32 + bp]);
            hb[k * 48 + (bp >> 2) * 6 + (bp & 3)] = hv;
        }
        __syncthreads();
        const ull* hbase = hb + bg * 6;
        for (int pass = 0; pass < 2; pass++) {
            const int myv0 = vb + pass * 352 + vql * 4;
            const float4* wp[4];
            bool vok[4];
#pragma unroll
            for (int vi = 0; vi < 4; vi++) {
                int v = myv0 + vi;
                vok[vi] = v < VOC;
                wp[vi] = (const float4*)(outW + (long)(vok[vi] ? v : 0) * HID);
            }
            float4 wc[4], wn[4];
#pragma unroll
            for (int vi = 0; vi < 4; vi++) wc[vi] = __ldg(wp[vi]);
            ull acc[4][4] = {};
            for (int q = 0; q < 75; q++) {
                if (q < 74) {
#pragma unroll
                    for (int vi = 0; vi < 4; vi++) wn[vi] = __ldg(wp[vi] + q + 1);
                }
                const ull* hq = hbase + (q * 4) * 48;
#pragma unroll
                for (int kk = 0; kk < 4; kk++) {
                    ulonglong2 hA = *(const ulonglong2*)(hq + kk * 48);
                    ulonglong2 hB = *(const ulonglong2*)(hq + kk * 48 + 2);
                    ull hh[4] = {hA.x, hA.y, hB.x, hB.y};
#pragma unroll
                    for (int vi = 0; vi < 4; vi++) {
                        float wsc[4] = {wc[vi].x, wc[vi].y, wc[vi].z, wc[vi].w};
                        ull wd = pack2(wsc[kk], wsc[kk]);
#pragma unroll
                        for (int bp = 0; bp < 4; bp++)
                            acc[vi][bp] = ffma2(wd, hh[bp], acc[vi][bp]);
                    }
                }
#pragma unroll
                for (int vi = 0; vi < 4; vi++) wc[vi] = wn[vi];
            }
            // epilogue: bias + argmax keys for this pass
            ull bst[8] = {};
#pragma unroll
            for (int vi = 0; vi < 4; vi++) {
                int v = myv0 + vi;
                if (v >= VOC) continue;
                float bb = __ldg(&outb[v]);
                unsigned lowb = 0xFFFFFFFFu - (unsigned)v;
#pragma unroll
                for (int bp = 0; bp < 4; bp++) {
                    float x, y; unpack2(acc[vi][bp], x, y);
                    ull kx = ((ull)ordf(x + bb) << 32) | lowb;
                    ull ky = ((ull)ordf(y + bb) << 32) | lowb;
                    if (kx > bst[2 * bp])     bst[2 * bp]     = kx;
                    if (ky > bst[2 * bp + 1]) bst[2 * bp + 1] = ky;
                }
            }
            // reduce across lanes sharing bg (lane, lane+8, +16, +24)
#pragma unroll
            for (int off = 16; off >= 8; off >>= 1)
#pragma unroll
                for (int j = 0; j < 8; j++) {
                    ull o = __shfl_down_sync(0xFFFFFFFFu, bst[j], off);
                    if (o > bst[j]) bst[j] = o;
                }
            if (lane < 8) {
                ull* row = &sb[warp * 64 + lane * 8];
#pragma unroll
                for (int j = 0; j < 8; j++) {
                    ull cur = (pass == 0) ? 0ULL : row[j];
                    row[j] = (bst[j] > cur) ? bst[j] : cur;
                }
            }
        }
        __syncthreads();
        if (tid < BSZ) {
            ull m = 0;
#pragma unroll 2
            for (int w = 0; w < 22; w++) {
                ull k = sb[w * 64 + tid];
                if (k > m) m = k;
            }
            atomicMax(&g_best2[par][tid], m);
        }
        grid_bar();
    }
    if (blockIdx.x == 0 && tid < BSZ) {
        ull key = __ldcg(&g_best2[(SEQ - 1) & 1][tid]);
        out[(SEQ - 1) * BSZ + tid] = (float)(int)(0xFFFFFFFFu - (unsigned)key);
    }
}

// ---------------- launch ----------------
extern "C" void kernel_launch(void* const* d_in, const int* in_sizes, int n_in,
                              void* d_out, int out_size) {
    const int*   input = (const int*)d_in[0];
    const float* emb   = (const float*)d_in[1];
    const float* eWih  = (const float*)d_in[2];
    const float* eWhh  = (const float*)d_in[3];
    const float* ebih  = (const float*)d_in[4];
    const float* ebhh  = (const float*)d_in[5];
    const float* dWih  = (const float*)d_in[6];
    const float* dWhh  = (const float*)d_in[7];
    const float* dbih  = (const float*)d_in[8];
    const float* dbhh  = (const float*)d_in[9];
    const float* outW  = (const float*)d_in[10];
    const float* outb  = (const float*)d_in[11];
    float* out = (float*)d_out;

    cudaFuncSetAttribute(k_encpre, cudaFuncAttributeMaxDynamicSharedMemorySize, SM_ENCPRE);
    cudaFuncSetAttribute(k_enc,    cudaFuncAttributeMaxDynamicSharedMemorySize, SM_ENC);
    cudaFuncSetAttribute(k_dec,    cudaFuncAttributeMaxDynamicSharedMemorySize, SM_DEC);

    k_init<<<38, 256>>>();
    k_encpre<<<dim3(15, 64), 256, SM_ENCPRE>>>(input, emb, eWih, ebih);
    k_enc<<<NB, 512, SM_ENC>>>(eWhh, ebhh);
    k_dec<<<NB, THR, SM_DEC>>>(emb, dWih, dWhh, dbih, dbhh, outW, outb, out);
}

// round 14
// speedup vs baseline: 1.4278x; 1.2219x over previous
#include <cuda_runtime.h>

#define BSZ 64
#define HID 300
#define SEQ 64
#define VOC 100000
#define NB  148
#define THR 704                  // 22 warps

typedef unsigned long long ull;

// ---------------- scratch ----------------
__device__ float2 g_hp[2][HID * 32];            // packed h, double buffered
__device__ float2 g_egi[SEQ * 900 * 32];        // precomputed encoder input gates (+bias)
__device__ ull    g_best2[2][BSZ];              // per-step argmax keys, double buffered
__device__ unsigned g_barcnt, g_bargen;

// ---------------- helpers ----------------
__device__ __forceinline__ unsigned ordf(float f) {
    unsigned u = __float_as_uint(f);
    return (u & 0x80000000u) ? ~u : (u | 0x80000000u);
}
__device__ __forceinline__ ull pack2(float lo, float hi) {
    ull r;
    asm("mov.b64 %0, {%1,%2};" : "=l"(r) : "f"(lo), "f"(hi));
    return r;
}
__device__ __forceinline__ void unpack2(ull v, float& lo, float& hi) {
    asm("mov.b64 {%0,%1}, %2;" : "=f"(lo), "=f"(hi) : "l"(v));
}
__device__ __forceinline__ ull ffma2(ull a, ull b, ull c) {
    ull d;
    asm("fma.rn.f32x2 %0, %1, %2, %3;" : "=l"(d) : "l"(a), "l"(b), "l"(c));
    return d;
}

// grid-wide barrier; all NB blocks co-resident (1 block/SM).
__device__ __forceinline__ void grid_bar() {
    __threadfence();
    __syncthreads();
    if (threadIdx.x == 0) {
        unsigned gen = atomicAdd(&g_bargen, 0u);
        if (atomicAdd(&g_barcnt, 1u) == (unsigned)(NB - 1)) {
            atomicExch(&g_barcnt, 0u);
            __threadfence();
            atomicAdd(&g_bargen, 1u);
        } else {
            while (atomicAdd(&g_bargen, 0u) == gen) __nanosleep(64);
        }
    }
    __syncthreads();
}

// ---------------- init ----------------
__global__ void k_init() {
    int i = blockIdx.x * blockDim.x + threadIdx.x;
    if (i < HID * 32) g_hp[0][i] = make_float2(0.f, 0.f);
    if (i == 0) { g_barcnt = 0u; g_bargen = 0u; }
}

// ---------------- encoder input-gate pre-GEMM (all 64 steps, one launch) -------
#define SM_ENCPRE (16320 + 31680 + 256)
__global__ void k_encpre(const int* __restrict__ input, const float* __restrict__ emb,
                         const float* __restrict__ W, const float* __restrict__ bias) {
    extern __shared__ char sm[];
    float2* x_s = (float2*)sm;               // [60][34]
    float2* w_s = (float2*)(sm + 16320);     // [60][66] duplicated
    int* sid    = (int*)(sm + 16320 + 31680);
    const int tid = threadIdx.x;
    const int t = blockIdx.y, j0 = blockIdx.x * 64;
    if (tid < BSZ) sid[tid] = input[t * BSZ + tid];
    __syncthreads();
    const int tx = tid & 15, ty = tid >> 4;
    ull acc[2][4] = {};
    for (int k0 = 0; k0 < HID; k0 += 60) {
        for (int idx = tid; idx < 32 * 60; idx += 256) {
            int k = idx >> 5, bp = idx & 31;
            float e0 = emb[(long)sid[2 * bp] * HID + k0 + k];
            float e1 = emb[(long)sid[2 * bp + 1] * HID + k0 + k];
            x_s[k * 34 + bp] = make_float2(e0, e1);
        }
        for (int idx = tid; idx < 64 * 15; idx += 256) {
            int j = idx / 15, q = idx % 15;
            int jg = j0 + j;
            float4 w = (jg < 900) ? *(const float4*)&W[(long)jg * HID + k0 + q * 4]
                                  : make_float4(0, 0, 0, 0);
            w_s[(q * 4 + 0) * 66 + j] = make_float2(w.x, w.x);
            w_s[(q * 4 + 1) * 66 + j] = make_float2(w.y, w.y);
            w_s[(q * 4 + 2) * 66 + j] = make_float2(w.z, w.z);
            w_s[(q * 4 + 3) * 66 + j] = make_float2(w.w, w.w);
        }
        __syncthreads();
#pragma unroll 4
        for (int k = 0; k < 60; k++) {
            ull xp0 = *(const ull*)&x_s[k * 34 + ty];
            ull xp1 = *(const ull*)&x_s[k * 34 + ty + 16];
            ulonglong2 wA = *(const ulonglong2*)&w_s[k * 66 + tx * 4];
            ulonglong2 wB = *(const ulonglong2*)&w_s[k * 66 + tx * 4 + 2];
            acc[0][0] = ffma2(xp0, wA.x, acc[0][0]);
            acc[1][0] = ffma2(xp1, wA.x, acc[1][0]);
            acc[0][1] = ffma2(xp0, wA.y, acc[0][1]);
            acc[1][1] = ffma2(xp1, wA.y, acc[1][1]);
            acc[0][2] = ffma2(xp0, wB.x, acc[0][2]);
            acc[1][2] = ffma2(xp1, wB.x, acc[1][2]);
            acc[0][3] = ffma2(xp0, wB.y, acc[0][3]);
            acc[1][3] = ffma2(xp1, wB.y, acc[1][3]);
        }
        __syncthreads();
    }
#pragma unroll
    for (int jj = 0; jj < 4; jj++) {
        int j = j0 + tx * 4 + jj;
        if (j >= 900) continue;
        float bb = bias[j];
#pragma unroll
        for (int p = 0; p < 2; p++) {
            int bp = ty + 16 * p;
            float a, b; unpack2(acc[p][jj], a, b);
            g_egi[((long)t * 900 + j) * 32 + bp] = make_float2(a + bb, b + bb);
        }
    }
}

// ---------------- persistent encoder (512 thr): weights resident ---------------
#define SM_ENC (76800 + 21600 + 9216 + 32)
__global__ void __launch_bounds__(512, 1) k_enc(const float* __restrict__ Whh,
                                                const float* __restrict__ bhh) {
    extern __shared__ char sm[];
    float2* Hn = (float2*)sm;
    float2* Wg = (float2*)(sm + 76800);
    ull*   red = (ull*)(sm + 76800 + 21600);
    const int tid = threadIdx.x, warp = tid >> 5, lane = tid & 31;
    const int bid = blockIdx.x;
    const int nr = (bid < 4) ? 3 : 2;

    for (int i = tid; i < nr * 3 * 75; i += 512) {
        int row = i / 75, q = i % 75;
        int rl = row / 3, g = row % 3;
        int grow = g * HID + bid + rl * NB;
        float4 w = *(const float4*)&Whh[(long)grow * HID + q * 4];
        float2* d2 = &Wg[row * 300 + q * 4];
        d2[0] = make_float2(w.x, w.x); d2[1] = make_float2(w.y, w.y);
        d2[2] = make_float2(w.z, w.z); d2[3] = make_float2(w.w, w.w);
    }
    __syncthreads();

    for (int t = 0; t < SEQ; t++) {
        const int par = t & 1;
        for (int i = tid; i < 4800; i += 512)
            ((uint4*)Hn)[i] = __ldcg((const uint4*)&g_hp[par][0] + i);
        __syncthreads();
        const int rl = warp >> 2, kq = warp & 3;
        if (rl < nr) {
            ull a0 = 0, a1 = 0, a2 = 0;
            const float2* wb = &Wg[rl * 900];
            const int kend = kq * 75 + 75;
#pragma unroll 3
            for (int k = kq * 75; k < kend; k++) {
                ull hv = *(const ull*)&Hn[k * 32 + lane];
                a0 = ffma2(hv, *(const ull*)&wb[k], a0);
                a1 = ffma2(hv, *(const ull*)&wb[300 + k], a1);
                a2 = ffma2(hv, *(const ull*)&wb[600 + k], a2);
            }
            red[((rl * 4 + kq) * 3 + 0) * 32 + lane] = a0;
            red[((rl * 4 + kq) * 3 + 1) * 32 + lane] = a1;
            red[((rl * 4 + kq) * 3 + 2) * 32 + lane] = a2;
        }
        __syncthreads();
        if (warp < nr) {
            const int row = bid + warp * NB;
            float s[3][2];
#pragma unroll
            for (int g = 0; g < 3; g++) {
                float acx = 0.f, acy = 0.f;
#pragma unroll
                for (int kq2 = 0; kq2 < 4; kq2++) {
                    float a, b;
                    unpack2(red[((warp * 4 + kq2) * 3 + g) * 32 + lane], a, b);
                    acx += a; acy += b;
                }
                s[g][0] = acx; s[g][1] = acy;
            }
            float bhr = bhh[row], bhz = bhh[HID + row], bhn = bhh[2 * HID + row];
            float2 er = g_egi[((long)t * 900 + row) * 32 + lane];
            float2 ez = g_egi[((long)t * 900 + 300 + row) * 32 + lane];
            float2 en = g_egi[((long)t * 900 + 600 + row) * 32 + lane];
            float2 hold = Hn[row * 32 + lane];
            float gr[2] = {er.x, er.y}, gz[2] = {ez.x, ez.y}, gn[2] = {en.x, en.y};
            float ho[2] = {hold.x, hold.y}, o2[2];
#pragma unroll
            for (int p = 0; p < 2; p++) {
                float r = 1.f / (1.f + expf(-(gr[p] + s[0][p] + bhr)));
                float z = 1.f / (1.f + expf(-(gz[p] + s[1][p] + bhz)));
                float n = tanhf(gn[p] + r * (s[2][p] + bhn));
                o2[p] = (1.f - z) * n + z * ho[p];
            }
            g_hp[par ^ 1][row * 32 + lane] = make_float2(o2[0], o2[1]);
        }
        grid_bar();
    }
}

// ---------------- persistent decoder, 704 threads ------------------------------
// smem layout:
//   WgA  @0       (21632)  persistent decoder GRU weights (staged once)
//   hb   @21632   (115200) phase B: h natural pairs, 48-ull k-stride (bank-clean)
//   wsb  @136832  (50688)  phase B: per-warp w buffers, 16 rows x 144B each
//   sb   @187520  (11264)  phase B: per-warp argmax table
//   sid  @198784  (256)
//   Hn   @21632   (76800)  phase A (overlays hb)
//   X    @98432   (79200)  phase A (overlays hb tail + wsb head; disjoint in time)
//   red  @177632  (18432)  phase A (overlays wsb tail; disjoint in time)
#define OFF_HB  21632
#define OFF_WSB 136832
#define OFF_SB  187520
#define OFF_SID 198784
#define OFF_X   98432
#define OFF_RED 177632
#define SM_DEC  199040
#define WROWB   144                 // bytes per buffered w row (128 data + 16 pad)
__global__ void __launch_bounds__(THR, 1) k_dec(
    const float* __restrict__ emb,
    const float* __restrict__ Wih, const float* __restrict__ Whh,
    const float* __restrict__ bih, const float* __restrict__ bhh,
    const float* __restrict__ outW, const float* __restrict__ outb,
    float* __restrict__ out) {
    extern __shared__ char sm[];
    float*  WgA = (float*)sm;
    ull*    hb  = (ull*)(sm + OFF_HB);
    float2* Hn  = (float2*)(sm + OFF_HB);
    char*   wsb = sm + OFF_WSB;
    ull*    sb  = (ull*)(sm + OFF_SB);
    int*    sid = (int*)(sm + OFF_SID);
    float*  X   = (float*)(sm + OFF_X);
    ull*    red = (ull*)(sm + OFF_RED);

    const int tid = threadIdx.x, warp = tid >> 5, lane = tid & 31;
    const int bid = blockIdx.x;
    const int nr = (bid < 4) ? 3 : 2;
    const int vb = bid * 675 + (bid < 100 ? bid : 100);
    const int bg = tid & 7;          // b-group (consume): b = bg*8 .. bg*8+7
    const int vq = (tid >> 3) & 3;   // v-quad within warp (consume + staging role)
    const int js = lane & 7;         // k-piece within row (staging role)
    char* mywb = wsb + warp * (16 * WROWB);
    const long WMAX = (long)VOC * HID - 4;   // clamp base for float4 reads

    // stage decoder GRU weights ONCE (persistent for all 64 steps)
    for (int i = tid; i < nr * 6 * 75; i += THR) {
        int row = i / 75, q = i % 75;
        int rl = row / 6, g = row % 6;
        const float* W = (g < 3) ? Wih : Whh;
        int grow = (g % 3) * HID + bid + rl * NB;
        float4 w = __ldg((const float4*)&W[(long)grow * HID + q * 4]);
        float* dd = &WgA[row * 300 + q * 4];
        dd[0] = w.x; dd[1] = w.y; dd[2] = w.z; dd[3] = w.w;
    }
    __syncthreads();

    for (int d = 0; d < SEQ; d++) {
        const int par = d & 1;
        // ===== phase A: ids, stage h/x, GRU step =====
        if (tid < BSZ) {
            int myid = 0;
            if (d > 0) {
                ull key = __ldcg(&g_best2[par ^ 1][tid]);
                myid = (int)(0xFFFFFFFFu - (unsigned)key);
                if (bid == 0) out[(d - 1) * BSZ + tid] = (float)myid;
            }
            sid[tid] = myid;
            if (bid == 0) g_best2[par][tid] = 0ULL;
        }
        for (int i = tid; i < 4800; i += THR)
            ((uint4*)Hn)[i] = __ldcg((const uint4*)&g_hp[par][0] + i);
        __syncthreads();
        for (int i = tid; i < 64 * 75; i += THR) {
            int b = i / 75, q = i % 75;
            float4 e = __ldg((const float4*)&emb[(long)sid[b] * HID + q * 4]);
            X[(q * 4 + 0) * 66 + b] = fmaxf(e.x, 0.f);
            X[(q * 4 + 1) * 66 + b] = fmaxf(e.y, 0.f);
            X[(q * 4 + 2) * 66 + b] = fmaxf(e.z, 0.f);
            X[(q * 4 + 3) * 66 + b] = fmaxf(e.w, 0.f);
        }
        __syncthreads();
        if (warp < 16) {
            const int rl = warp >> 2, kq = warp & 3;
            if (rl < nr) {
                ull a6[6] = {};
                const float* wb = &WgA[rl * 1800];
                const int kend = kq * 75 + 75;
                for (int k = kq * 75; k < kend; k++) {
                    ull hv = *(const ull*)&Hn[k * 32 + lane];
                    ull xv = *(const ull*)&X[k * 66 + lane * 2];
#pragma unroll
                    for (int g = 0; g < 6; g++) {
                        float w = wb[g * 300 + k];
                        a6[g] = ffma2((g < 3) ? xv : hv, pack2(w, w), a6[g]);
                    }
                }
#pragma unroll
                for (int g = 0; g < 6; g++)
                    red[((rl * 4 + kq) * 6 + g) * 32 + lane] = a6[g];
            }
        }
        __syncthreads();
        if (warp < nr) {
            const int row = bid + warp * NB;
            float s[6][2];
#pragma unroll
            for (int g = 0; g < 6; g++) {
                float acx = 0.f, acy = 0.f;
#pragma unroll
                for (int kq2 = 0; kq2 < 4; kq2++) {
                    float a, b;
                    unpack2(red[((warp * 4 + kq2) * 6 + g) * 32 + lane], a, b);
                    acx += a; acy += b;
                }
                s[g][0] = acx; s[g][1] = acy;
            }
            float bir = bih[row], biz = bih[HID + row], bin = bih[2 * HID + row];
            float bhr = bhh[row], bhz = bhh[HID + row], bhn = bhh[2 * HID + row];
            float2 hold = Hn[row * 32 + lane];
            float ho[2] = {hold.x, hold.y}, o2[2];
#pragma unroll
            for (int p = 0; p < 2; p++) {
                float r = 1.f / (1.f + expf(-(s[0][p] + bir + s[3][p] + bhr)));
                float z = 1.f / (1.f + expf(-(s[1][p] + biz + s[4][p] + bhz)));
                float n = tanhf(s[2][p] + bin + r * (s[5][p] + bhn));
                o2[p] = (1.f - z) * n + z * ho[p];
            }
            g_hp[par ^ 1][row * 32 + lane] = make_float2(o2[0], o2[1]);
        }
        grid_bar();

        // ===== phase B: logits + argmax (warp-private w staging, no block bars) =====
        for (int i = tid; i < 9600; i += THR) {
            int k = i >> 5, bp = i & 31;
            ull hv = __ldcg((const ull*)&g_hp[par ^ 1][k * 32 + bp]);
            hb[k * 48 + (bp >> 2) * 6 + (bp & 3)] = hv;
        }
        __syncthreads();
        const ull* hbase = hb + bg * 6;
        for (int pass = 0; pass < 2; pass++) {
            const int vbw  = vb + pass * 352 + warp * 16;   // warp's 16-row base
            const int myv0 = vbw + vq * 4;                  // this thread's 4 v (vi 0..3)
            float4 wreg[4];
            // prologue: fetch chunk 0 (rows vbw + vq*4 + i, k pieces js*4..+3)
#pragma unroll
            for (int i = 0; i < 4; i++) {
                long fid = (long)(vbw + vq * 4 + i) * HID + js * 4;
                if (fid > WMAX) fid = WMAX;
                wreg[i] = __ldg((const float4*)&outW[fid]);
            }
            ull acc[4][4] = {};
            for (int c = 0; c < 10; c++) {
                __syncwarp();
                // store chunk c: buffer row (i*4+vq), 16B piece js
#pragma unroll
                for (int i = 0; i < 4; i++)
                    *(float4*)(mywb + (i * 4 + vq) * WROWB + js * 16) = wreg[i];
                __syncwarp();
                if (c < 9) {
#pragma unroll
                    for (int i = 0; i < 4; i++) {
                        long fid = (long)(vbw + vq * 4 + i) * HID + (c + 1) * 32 + js * 4;
                        if (fid > WMAX) fid = WMAX;
                        wreg[i] = __ldg((const float4*)&outW[fid]);
                    }
                }
                const int nq = (c == 9) ? 3 : 8;
                for (int qi = 0; qi < nq; qi++) {
                    float4 w4[4];
#pragma unroll
                    for (int vi = 0; vi < 4; vi++)
                        w4[vi] = *(const float4*)(mywb + (vi * 4 + vq) * WROWB + qi * 16);
                    const ull* hq = hbase + (c * 32 + qi * 4) * 48;
#pragma unroll
                    for (int kk = 0; kk < 4; kk++) {
                        ulonglong2 hA = *(const ulonglong2*)(hq + kk * 48);
                        ulonglong2 hB = *(const ulonglong2*)(hq + kk * 48 + 2);
                        ull hh[4] = {hA.x, hA.y, hB.x, hB.y};
#pragma unroll
                        for (int vi = 0; vi < 4; vi++) {
                            float wsc = (&w4[vi].x)[kk];
                            ull wd = pack2(wsc, wsc);
#pragma unroll
                            for (int bp = 0; bp < 4; bp++)
                                acc[vi][bp] = ffma2(wd, hh[bp], acc[vi][bp]);
                        }
                    }
                }
            }
            // epilogue: bias + argmax keys for this pass
            ull bst[8] = {};
#pragma unroll
            for (int vi = 0; vi < 4; vi++) {
                int v = myv0 + vi;
                if (v >= VOC) continue;
                float bb = __ldg(&outb[v]);
                unsigned lowb = 0xFFFFFFFFu - (unsigned)v;
#pragma unroll
                for (int bp = 0; bp < 4; bp++) {
                    float x, y; unpack2(acc[vi][bp], x, y);
                    ull kx = ((ull)ordf(x + bb) << 32) | lowb;
                    ull ky = ((ull)ordf(y + bb) << 32) | lowb;
                    if (kx > bst[2 * bp])     bst[2 * bp]     = kx;
                    if (ky > bst[2 * bp + 1]) bst[2 * bp + 1] = ky;
                }
            }
            // reduce across the 4 vq lanes sharing bg (lane, lane+8, +16, +24)
#pragma unroll
            for (int off = 16; off >= 8; off >>= 1)
#pragma unroll
                for (int j = 0; j < 8; j++) {
                    ull o = __shfl_down_sync(0xFFFFFFFFu, bst[j], off);
                    if (o > bst[j]) bst[j] = o;
                }
            if (lane < 8) {
                ull* row = &sb[warp * 64 + lane * 8];
#pragma unroll
                for (int j = 0; j < 8; j++) {
                    ull cur = (pass == 0) ? 0ULL : row[j];
                    row[j] = (bst[j] > cur) ? bst[j] : cur;
                }
            }
        }
        __syncthreads();
        if (tid < BSZ) {
            ull m = 0;
#pragma unroll 2
            for (int w = 0; w < 22; w++) {
                ull k = sb[w * 64 + tid];
                if (k > m) m = k;
            }
            atomicMax(&g_best2[par][tid], m);
        }
        grid_bar();
    }
    if (blockIdx.x == 0 && tid < BSZ) {
        ull key = __ldcg(&g_best2[(SEQ - 1) & 1][tid]);
        out[(SEQ - 1) * BSZ + tid] = (float)(int)(0xFFFFFFFFu - (unsigned)key);
    }
}

// ---------------- launch ----------------
extern "C" void kernel_launch(void* const* d_in, const int* in_sizes, int n_in,
                              void* d_out, int out_size) {
    const int*   input = (const int*)d_in[0];
    const float* emb   = (const float*)d_in[1];
    const float* eWih  = (const float*)d_in[2];
    const float* eWhh  = (const float*)d_in[3];
    const float* ebih  = (const float*)d_in[4];
    const float* ebhh  = (const float*)d_in[5];
    const float* dWih  = (const float*)d_in[6];
    const float* dWhh  = (const float*)d_in[7];
    const float* dbih  = (const float*)d_in[8];
    const float* dbhh  = (const float*)d_in[9];
    const float* outW  = (const float*)d_in[10];
    const float* outb  = (const float*)d_in[11];
    float* out = (float*)d_out;

    cudaFuncSetAttribute(k_encpre, cudaFuncAttributeMaxDynamicSharedMemorySize, SM_ENCPRE);
    cudaFuncSetAttribute(k_enc,    cudaFuncAttributeMaxDynamicSharedMemorySize, SM_ENC);
    cudaFuncSetAttribute(k_dec,    cudaFuncAttributeMaxDynamicSharedMemorySize, SM_DEC);

    k_init<<<38, 256>>>();
    k_encpre<<<dim3(15, 64), 256, SM_ENCPRE>>>(input, emb, eWih, ebih);
    k_enc<<<NB, 512, SM_ENC>>>(eWhh, ebhh);
    k_dec<<<NB, THR, SM_DEC>>>(emb, dWih, dWhh, dbih, dbhh, outW, outb, out);
}